// round 2
// baseline (speedup 1.0000x reference)
#include <cuda_runtime.h>
#include <cuda_bf16.h>
#include <cstdint>

#define NG   32
#define NPG  1024
#define NN   (NG*NPG)
#define HD   128
#define NLAY 4
#define NPAR 256
#define NPT  (NG*NPAR)
#define NCLS 50
#define DCCN 16
#define CS   (DCCN*NCLS)   // 800

// ---------------- device scratch ----------------
__device__ __align__(256) float g_h0[NN*HD];
__device__ __align__(256) float g_f0[NN*HD];
__device__ __align__(256) float g_f1[NN*HD];
__device__ __align__(256) float g_f2[NN*HD];
__device__ __align__(256) float g_f3[NN*HD];
__device__ __align__(256) float g_GL[NPT*HD];
__device__ __align__(256) float g_GR[NPT*HD];
__device__ __align__(256) float g_u [NG*1024*4];
__device__ __align__(256) float g_Vc[NG*1024*4];
__device__ __align__(256) float g_m [NG*1024];
__device__ __align__(256) float g_iZ[NG*1024];
__device__ __align__(256) float g_SC[NG*1024*4];
__device__ __align__(256) float g_V [(size_t)NG*1024*CS];   // 104.9 MB  [b][n][c*50+s]
__device__ __align__(256) float g_delta[NN*NCLS];
__device__ __align__(256) float g_gamma[NN*NCLS];
__device__ __align__(256) float g_zs[NG*CS];
__device__ __align__(256) float g_z [NG*CS];

__device__ __forceinline__ float* featptr(int l){
    switch(l){ case 0: return g_f0; case 1: return g_f1; case 2: return g_f2; default: return g_f3; }
}

// ---------------- embedding + leaf prefill ----------------
__global__ void k_embed(const int* __restrict__ type_ids, const int* __restrict__ token_ids,
                        const float* __restrict__ temb, const float* __restrict__ kemb){
    int idx = blockIdx.x*256 + threadIdx.x;
    int n = idx >> 7, d = idx & 127;
    float v = (d < 64) ? temb[(size_t)type_ids[n]*64 + d] : kemb[(size_t)token_ids[n]*64 + (d-64)];
    g_h0[idx] = v;
    if ((n & (NPG-1)) >= NPAR){ g_f0[idx]=v; g_f1[idx]=v; g_f2[idx]=v; g_f3[idx]=v; }
}

// ---------------- weighted child gather (structural, no atomics) ----------------
__global__ void k_gather(const int* __restrict__ src, const float* __restrict__ lw,
                         const float* __restrict__ rw, int layer){
    int idx = blockIdx.x*256 + threadIdx.x;          // prow*128 + d
    int prow = idx >> 7, d = idx & 127;
    int g = prow >> 8, p = prow & 255;
    const float* hin = (layer==0) ? g_h0 : featptr(layer-1);
    int ebase = g*1023 + p*4;
    int nch = (p == 255) ? 3 : 4;
    float gl = 0.f, gr = 0.f;
    for (int j = 0; j < nch; j++){
        int e = ebase + j;
        int s = src[e];
        float v = hin[(size_t)s*HD + d];
        gl += lw[e]*v;  gr += rw[e]*v;
    }
    g_GL[idx] = gl;  g_GR[idx] = gr;
}

// ---------------- fused GEMM: feats[l] = relu(GL@WL + GR@WR + Hp@WT + b) ----------------
__global__ __launch_bounds__(256) void k_gemm(const float* __restrict__ WLp,
        const float* __restrict__ WRp, const float* __restrict__ WTp,
        const float* __restrict__ bconv, int layer){
    __shared__ __align__(16) float Xs[16][72];
    __shared__ __align__(16) float Ws[16][128];
    const int tid = threadIdx.x;
    const int row0 = blockIdx.x*64;                   // [0, 8192)
    const int g = row0 >> 8, l0 = row0 & 255;
    const float* hin = (layer==0) ? g_h0 : featptr(layer-1);
    const float* Abase[3] = { g_GL + (size_t)row0*HD,
                              g_GR + (size_t)row0*HD,
                              hin + (size_t)(g*NPG + l0)*HD };
    const float* Wb[3] = { WLp + layer*HD*HD, WRp + layer*HD*HD, WTp + layer*HD*HD };
    const int ty = tid >> 5, tx = tid & 31;
    float acc[8][4];
    #pragma unroll
    for (int i=0;i<8;i++){ acc[i][0]=0.f; acc[i][1]=0.f; acc[i][2]=0.f; acc[i][3]=0.f; }

    for (int seg = 0; seg < 3; seg++){
        const float* A = Abase[seg];
        const float* W = Wb[seg];
        for (int k0 = 0; k0 < HD; k0 += 16){
            __syncthreads();
            {   int m = tid >> 2, k4 = tid & 3;
                float4 v = *(const float4*)(A + (size_t)m*HD + k0 + k4*4);
                Xs[k4*4+0][m]=v.x; Xs[k4*4+1][m]=v.y; Xs[k4*4+2][m]=v.z; Xs[k4*4+3][m]=v.w; }
            #pragma unroll
            for (int i=0;i<2;i++){
                int q = tid + i*256;
                int k = q >> 5, n4 = q & 31;
                *(float4*)&Ws[k][n4*4] = *(const float4*)(W + (size_t)(k0+k)*HD + n4*4);
            }
            __syncthreads();
            #pragma unroll
            for (int k=0;k<16;k++){
                float4 b = *(const float4*)&Ws[k][tx*4];
                float4 a0 = *(const float4*)&Xs[k][ty*8];
                float4 a1 = *(const float4*)&Xs[k][ty*8+4];
                float av[8] = {a0.x,a0.y,a0.z,a0.w,a1.x,a1.y,a1.z,a1.w};
                #pragma unroll
                for (int i=0;i<8;i++){
                    acc[i][0] += av[i]*b.x; acc[i][1] += av[i]*b.y;
                    acc[i][2] += av[i]*b.z; acc[i][3] += av[i]*b.w;
                }
            }
        }
    }
    float* fo = featptr(layer);
    float4 bb = *(const float4*)(bconv + layer*HD + tx*4);
    #pragma unroll
    for (int i=0;i<8;i++){
        int local = l0 + ty*8 + i;
        float4 o;
        o.x = fmaxf(acc[i][0]+bb.x, 0.f);
        o.y = fmaxf(acc[i][1]+bb.y, 0.f);
        o.z = fmaxf(acc[i][2]+bb.z, 0.f);
        o.w = fmaxf(acc[i][3]+bb.w, 0.f);
        *(float4*)(fo + (size_t)(g*NPG + local)*HD + tx*4) = o;
    }
}

// ---------------- VTS: l2, top-8, gather u, init Vcum ----------------
__global__ __launch_bounds__(1024) void k_l2top(){
    __shared__ float l2s[1024];
    __shared__ float rv[32]; __shared__ int ri[32];
    __shared__ int top8[8];
    int g = blockIdx.x, tid = threadIdx.x;
    int lane = tid & 31, warp = tid >> 5;
    l2s[tid] = 0.f;
    __syncthreads();
    const float* fs[4] = {g_f0, g_f1, g_f2, g_f3};
    for (int l=0;l<4;l++){
        const float* f = fs[l] + (size_t)g*NPG*HD;
        for (int off=0; off<NPG*HD; off+=1024){
            float v = f[off + tid];
            float sq = v*v;
            #pragma unroll
            for (int o=16;o;o>>=1) sq += __shfl_xor_sync(0xffffffffu, sq, o);
            if (lane == 0) atomicAdd(&l2s[(off + tid) >> 7], sq);
        }
    }
    __syncthreads();
    for (int t=0;t<8;t++){
        float v = l2s[tid]; int idx = tid;
        #pragma unroll
        for (int o=16;o;o>>=1){
            float v2 = __shfl_xor_sync(0xffffffffu, v, o);
            int   i2 = __shfl_xor_sync(0xffffffffu, idx, o);
            if (v2 > v || (v2 == v && i2 < idx)){ v = v2; idx = i2; }
        }
        if (lane == 0){ rv[warp] = v; ri[warp] = idx; }
        __syncthreads();
        if (warp == 0){
            float vv = rv[lane]; int ii = ri[lane];
            #pragma unroll
            for (int o=16;o;o>>=1){
                float v2 = __shfl_xor_sync(0xffffffffu, vv, o);
                int   i2 = __shfl_xor_sync(0xffffffffu, ii, o);
                if (v2 > vv || (v2 == vv && i2 < ii)){ vv = v2; ii = i2; }
            }
            if (lane == 0){ top8[t] = ii; l2s[ii] = -1e30f; }
        }
        __syncthreads();
    }
    int bcap = tid >> 7, hh = tid & 127;
    int node = top8[bcap];
    size_t nb = (size_t)(g*NPG + node)*HD + hh;
    float4 uv;
    uv.x = g_f0[nb]; uv.y = g_f1[nb]; uv.z = g_f2[nb]; uv.w = g_f3[nb];
    *(float4*)&g_u [(size_t)(g*1024 + tid)*4] = uv;
    *(float4*)&g_Vc[(size_t)(g*1024 + tid)*4] = uv;
}

// ---------------- VTS phase A: per-row max + 1/Z of alpha = u . Vcum ----------------
__global__ __launch_bounds__(256) void k_phaseA(){
    __shared__ __align__(16) float sV[4096];
    int g = blockIdx.x, tid = threadIdx.x;
    int row = blockIdx.y*256 + tid;
    for (int i=tid;i<4096;i+=256) sV[i] = g_Vc[(size_t)g*4096 + i];
    __syncthreads();
    float4 u = *(const float4*)&g_u[(size_t)(g*1024 + row)*4];
    float m0=-1e30f, m1=-1e30f, m2=-1e30f, m3=-1e30f;
    for (int j=0;j<1024;j+=4){
        float4 c0 = *(const float4*)&sV[(j+0)*4];
        float4 c1 = *(const float4*)&sV[(j+1)*4];
        float4 c2 = *(const float4*)&sV[(j+2)*4];
        float4 c3 = *(const float4*)&sV[(j+3)*4];
        m0 = fmaxf(m0, u.x*c0.x + u.y*c0.y + u.z*c0.z + u.w*c0.w);
        m1 = fmaxf(m1, u.x*c1.x + u.y*c1.y + u.z*c1.z + u.w*c1.w);
        m2 = fmaxf(m2, u.x*c2.x + u.y*c2.y + u.z*c2.z + u.w*c2.w);
        m3 = fmaxf(m3, u.x*c3.x + u.y*c3.y + u.z*c3.z + u.w*c3.w);
    }
    float m = fmaxf(fmaxf(m0,m1), fmaxf(m2,m3));
    float z0=0.f, z1=0.f, z2=0.f, z3=0.f;
    for (int j=0;j<1024;j+=4){
        float4 c0 = *(const float4*)&sV[(j+0)*4];
        float4 c1 = *(const float4*)&sV[(j+1)*4];
        float4 c2 = *(const float4*)&sV[(j+2)*4];
        float4 c3 = *(const float4*)&sV[(j+3)*4];
        z0 += __expf(u.x*c0.x + u.y*c0.y + u.z*c0.z + u.w*c0.w - m);
        z1 += __expf(u.x*c1.x + u.y*c1.y + u.z*c1.z + u.w*c1.w - m);
        z2 += __expf(u.x*c2.x + u.y*c2.y + u.z*c2.z + u.w*c2.w - m);
        z3 += __expf(u.x*c3.x + u.y*c3.y + u.z*c3.z + u.w*c3.w - m);
    }
    g_m [g*1024 + row] = m;
    g_iZ[g*1024 + row] = 1.f/((z0+z1)+(z2+z3));
}

// ---------------- VTS phase B: v_new = beta^T u ; accumulate or squash ----------------
__global__ __launch_bounds__(256) void k_phaseB(int last){
    __shared__ __align__(16) float sU[4096];
    __shared__ float sM[1024];
    __shared__ float sZ[1024];
    int g = blockIdx.x, tid = threadIdx.x;
    int col = blockIdx.y*256 + tid;
    for (int i=tid;i<4096;i+=256) sU[i] = g_u[(size_t)g*4096 + i];
    for (int i=tid;i<1024;i+=256){ sM[i] = g_m[g*1024+i]; sZ[i] = g_iZ[g*1024+i]; }
    __syncthreads();
    float4 c = *(const float4*)&g_Vc[(size_t)(g*1024 + col)*4];
    float a0=0.f, a1=0.f, a2=0.f, a3=0.f;
    #pragma unroll 4
    for (int i=0;i<1024;i++){
        float4 uu = *(const float4*)&sU[i*4];
        float s = uu.x*c.x + uu.y*c.y + uu.z*c.z + uu.w*c.w;
        float w = __expf(s - sM[i]) * sZ[i];
        a0 += w*uu.x; a1 += w*uu.y; a2 += w*uu.z; a3 += w*uu.w;
    }
    if (!last){
        float4 o; o.x=c.x+a0; o.y=c.y+a1; o.z=c.z+a2; o.w=c.w+a3;
        *(float4*)&g_Vc[(size_t)(g*1024 + col)*4] = o;
    } else {
        float sq = a0*a0 + a1*a1 + a2*a2 + a3*a3;
        float sc = sq/(1.f+sq)/(sqrtf(sq + 1e-10f) + 1e-8f);
        float4 o; o.x=a0*sc; o.y=a1*sc; o.z=a2*sc; o.w=a3*sc;
        *(float4*)&g_SC[(size_t)(g*1024 + col)*4] = o;
    }
}

// ---------------- v[b,n,c,s] = dot4(Wjm[n,c,s,:], SC[b,n,:]) ----------------
__global__ void k_v(const float* __restrict__ Wjm){
    int bn = blockIdx.x;                       // b*1024 + n
    int n = bn & 1023;
    const float4* w = (const float4*)(Wjm + (size_t)n*(CS*4));
    float4 sc = *(const float4*)&g_SC[(size_t)bn*4];
    float* vo = g_V + (size_t)bn*CS;
    for (int idx = threadIdx.x; idx < CS; idx += 256){
        float4 ww = w[idx];
        vo[idx] = ww.x*sc.x + ww.y*sc.y + ww.z*sc.z + ww.w*sc.w;
    }
}

__global__ void k_zero_delta(){ int i = blockIdx.x*256+threadIdx.x; if (i < NN*NCLS) g_delta[i] = 0.f; }
__global__ void k_zero_zs(){ int i = blockIdx.x*256+threadIdx.x; if (i < NG*CS) g_zs[i] = 0.f; }

// ---------------- gamma = softmax_s(delta) ----------------
__global__ void k_gamma(){
    __shared__ float sd[3200];
    __shared__ float sm[64], sz[64];
    int base = blockIdx.x * 3200;              // 64 (b,n) rows x 50
    int tid = threadIdx.x;
    for (int i=tid;i<3200;i+=256) sd[i] = g_delta[(size_t)base + i];
    __syncthreads();
    if (tid < 64){
        float m = -1e30f;
        for (int k=0;k<NCLS;k++) m = fmaxf(m, sd[tid*NCLS + k]);
        float Z = 0.f;
        for (int k=0;k<NCLS;k++) Z += __expf(sd[tid*NCLS + k] - m);
        sm[tid] = m; sz[tid] = 1.f/Z;
    }
    __syncthreads();
    for (int i=tid;i<3200;i+=256){
        int r = i / NCLS;
        g_gamma[(size_t)base + i] = __expf(sd[i] - sm[r]) * sz[r];
    }
}

// ---------------- zsum[b,c,s] += sum_n gamma[b,n,s] v[b,n,c,s] ----------------
__global__ __launch_bounds__(800) void k_zsum(){
    __shared__ float sg[64*NCLS];
    int b = blockIdx.x, n0 = blockIdx.y*64;
    int tid = threadIdx.x;
    for (int i=tid;i<3200;i+=800) sg[i] = g_gamma[(size_t)(b*1024 + n0)*NCLS + i];
    __syncthreads();
    int s = tid % NCLS;
    float acc = 0.f;
    const float* vb = g_V + (size_t)(b*1024 + n0)*CS + tid;
    #pragma unroll 4
    for (int n=0;n<64;n++) acc += sg[n*NCLS + s] * vb[(size_t)n*CS];
    atomicAdd(&g_zs[b*CS + tid], acc);
}

// ---------------- z = squash_c(zsum) ----------------
__global__ void k_zfin(){
    int b = blockIdx.x, s = threadIdx.x;
    if (s >= NCLS) return;
    float vals[DCCN]; float sq = 0.f;
    #pragma unroll
    for (int c=0;c<DCCN;c++){ float v = g_zs[b*CS + c*NCLS + s]; vals[c]=v; sq += v*v; }
    float sc = sq/(1.f+sq)/(sqrtf(sq + 1e-10f) + 1e-8f);
    #pragma unroll
    for (int c=0;c<DCCN;c++) g_z[b*CS + c*NCLS + s] = vals[c]*sc;
}

// ---------------- delta[b,n,s] += sum_c v[b,n,c,s] z[b,c,s] ----------------
__global__ void k_delta(){
    int idx = blockIdx.x*256 + threadIdx.x;    // (b*1024+n)*50 + s
    if (idx >= NN*NCLS) return;
    int bn = idx / NCLS, s = idx % NCLS;
    int b = bn >> 10;
    const float* v = g_V + (size_t)bn*CS + s;
    const float* z = g_z + (size_t)b*CS + s;
    float acc = 0.f;
    #pragma unroll
    for (int c=0;c<DCCN;c++) acc += v[c*NCLS] * z[c*NCLS];
    g_delta[idx] += acc;
}

// ---------------- logits ----------------
__global__ void k_logit(float* __restrict__ out){
    int b = blockIdx.x, s = threadIdx.x;
    if (s >= NCLS) return;
    float sq = 0.f;
    #pragma unroll
    for (int c=0;c<DCCN;c++){ float v = g_z[b*CS + c*NCLS + s]; sq += v*v; }
    float lg = sqrtf(sq + 1e-10f);
    out[b*NCLS + s] = lg;
    out[NG*NCLS + b*NCLS + s] = lg;
}

// ---------------- launch ----------------
extern "C" void kernel_launch(void* const* d_in, const int* in_sizes, int n_in,
                              void* d_out, int out_size){
    const int*   type_ids  = (const int*)  d_in[0];
    const int*   token_ids = (const int*)  d_in[1];
    const int*   src       = (const int*)  d_in[2];
    const float* lw        = (const float*)d_in[4];
    const float* rw        = (const float*)d_in[5];
    const float* temb      = (const float*)d_in[7];
    const float* kemb      = (const float*)d_in[8];
    const float* WL        = (const float*)d_in[9];
    const float* WR        = (const float*)d_in[10];
    const float* WT        = (const float*)d_in[11];
    const float* bconv     = (const float*)d_in[12];
    const float* Wjm       = (const float*)d_in[13];
    float* out = (float*)d_out;

    k_embed<<<NN*HD/256, 256>>>(type_ids, token_ids, temb, kemb);
    for (int l = 0; l < NLAY; l++){
        k_gather<<<NPT*HD/256, 256>>>(src, lw, rw, l);
        k_gemm<<<NPT/64, 256>>>(WL, WR, WT, bconv, l);
    }
    k_l2top<<<NG, 1024>>>();
    for (int it = 0; it < 3; it++){
        k_phaseA<<<dim3(NG,4), 256>>>();
        k_phaseB<<<dim3(NG,4), 256>>>(it == 2 ? 1 : 0);
    }
    k_v<<<NG*1024, 256>>>(Wjm);
    k_zero_delta<<<NN*NCLS/256, 256>>>();
    for (int r = 0; r < 3; r++){
        k_gamma<<<NN*NCLS/3200, 256>>>();
        k_zero_zs<<<(NG*CS + 255)/256, 256>>>();
        k_zsum<<<dim3(NG,16), 800>>>();
        k_zfin<<<NG, 64>>>();
        if (r < 2) k_delta<<<(NN*NCLS + 255)/256, 256>>>();
    }
    k_logit<<<NG, 64>>>(out);
}

// round 4
// speedup vs baseline: 1.2118x; 1.2118x over previous
#include <cuda_runtime.h>
#include <cuda_bf16.h>
#include <cstdint>

#define NG   32
#define NPG  1024
#define NN   (NG*NPG)
#define HD   128
#define NLAY 4
#define NPAR 256
#define NPT  (NG*NPAR)
#define NCLS 50
#define DCCN 16
#define CS   (DCCN*NCLS)   // 800

// ---------------- device scratch ----------------
__device__ __align__(256) float g_h0[NN*HD];
__device__ __align__(256) float g_f0[NN*HD];
__device__ __align__(256) float g_f1[NN*HD];
__device__ __align__(256) float g_f2[NN*HD];
__device__ __align__(256) float g_f3[NN*HD];
__device__ __align__(256) float g_GL[NPT*HD];
__device__ __align__(256) float g_GR[NPT*HD];
__device__ __align__(256) float g_l2[NN];
__device__ __align__(256) float g_u [NG*1024*4];
__device__ __align__(256) float g_Vc[NG*1024*4];
__device__ __align__(256) float g_m [NG*1024];
__device__ __align__(256) float g_iZ[NG*1024];
__device__ __align__(256) float g_SC[NG*1024*4];
__device__ __align__(256) float g_delta[NN*NCLS];
__device__ __align__(256) float g_gamma[NN*NCLS];
__device__ __align__(256) float g_zs[NG*CS];
__device__ __align__(256) float g_z [NG*CS];

__device__ __forceinline__ float* featptr(int l){
    switch(l){ case 0: return g_f0; case 1: return g_f1; case 2: return g_f2; default: return g_f3; }
}

// ---------------- embedding + leaf prefill (float4) ----------------
__global__ void k_embed(const int* __restrict__ type_ids, const int* __restrict__ token_ids,
                        const float* __restrict__ temb, const float* __restrict__ kemb){
    int idx = blockIdx.x*256 + threadIdx.x;          // n*32 + q
    int n = idx >> 5, q = idx & 31;
    float4 v;
    if (q < 16) v = *(const float4*)(temb + (size_t)type_ids[n]*64 + q*4);
    else        v = *(const float4*)(kemb + (size_t)token_ids[n]*64 + (q-16)*4);
    size_t o = (size_t)n*HD + q*4;
    *(float4*)(g_h0 + o) = v;
    if ((n & (NPG-1)) >= NPAR){
        *(float4*)(g_f0+o)=v; *(float4*)(g_f1+o)=v; *(float4*)(g_f2+o)=v; *(float4*)(g_f3+o)=v;
    }
}

// ---------------- weighted child gather (structural, float4) ----------------
__global__ void k_gather(const int* __restrict__ src, const float* __restrict__ lw,
                         const float* __restrict__ rw, int layer){
    int idx = blockIdx.x*256 + threadIdx.x;          // prow*32 + q
    int prow = idx >> 5, q = idx & 31;
    int g = prow >> 8, p = prow & 255;
    const float* hin = (layer==0) ? g_h0 : featptr(layer-1);
    int ebase = g*1023 + p*4;
    int nch = (p == 255) ? 3 : 4;
    float4 gl = {0,0,0,0}, gr = {0,0,0,0};
    for (int j = 0; j < nch; j++){
        int e = ebase + j;
        int sN = src[e];
        float l = lw[e], r = rw[e];
        float4 v = *(const float4*)(hin + (size_t)sN*HD + q*4);
        gl.x += l*v.x; gl.y += l*v.y; gl.z += l*v.z; gl.w += l*v.w;
        gr.x += r*v.x; gr.y += r*v.y; gr.z += r*v.z; gr.w += r*v.w;
    }
    *(float4*)(g_GL + (size_t)prow*HD + q*4) = gl;
    *(float4*)(g_GR + (size_t)prow*HD + q*4) = gr;
}

// ---------------- fused GEMM: feats[l] = relu(GL@WL + GR@WR + Hp@WT + b) ----------------
__global__ __launch_bounds__(256) void k_gemm(const float* __restrict__ WLp,
        const float* __restrict__ WRp, const float* __restrict__ WTp,
        const float* __restrict__ bconv, int layer){
    __shared__ __align__(16) float Xs[16][72];
    __shared__ __align__(16) float Ws[16][128];
    const int tid = threadIdx.x;
    const int row0 = blockIdx.x*64;
    const int g = row0 >> 8, l0 = row0 & 255;
    const float* hin = (layer==0) ? g_h0 : featptr(layer-1);
    const float* Abase[3] = { g_GL + (size_t)row0*HD,
                              g_GR + (size_t)row0*HD,
                              hin + (size_t)(g*NPG + l0)*HD };
    const float* Wb[3] = { WLp + layer*HD*HD, WRp + layer*HD*HD, WTp + layer*HD*HD };
    const int ty = tid >> 5, tx = tid & 31;
    float acc[8][4];
    #pragma unroll
    for (int i=0;i<8;i++){ acc[i][0]=0.f; acc[i][1]=0.f; acc[i][2]=0.f; acc[i][3]=0.f; }

    for (int seg = 0; seg < 3; seg++){
        const float* A = Abase[seg];
        const float* W = Wb[seg];
        for (int k0 = 0; k0 < HD; k0 += 16){
            __syncthreads();
            {   int m = tid >> 2, k4 = tid & 3;
                float4 v = *(const float4*)(A + (size_t)m*HD + k0 + k4*4);
                Xs[k4*4+0][m]=v.x; Xs[k4*4+1][m]=v.y; Xs[k4*4+2][m]=v.z; Xs[k4*4+3][m]=v.w; }
            #pragma unroll
            for (int i=0;i<2;i++){
                int q = tid + i*256;
                int k = q >> 5, n4 = q & 31;
                *(float4*)&Ws[k][n4*4] = *(const float4*)(W + (size_t)(k0+k)*HD + n4*4);
            }
            __syncthreads();
            #pragma unroll
            for (int k=0;k<16;k++){
                float4 b = *(const float4*)&Ws[k][tx*4];
                float4 a0 = *(const float4*)&Xs[k][ty*8];
                float4 a1 = *(const float4*)&Xs[k][ty*8+4];
                float av[8] = {a0.x,a0.y,a0.z,a0.w,a1.x,a1.y,a1.z,a1.w};
                #pragma unroll
                for (int i=0;i<8;i++){
                    acc[i][0] += av[i]*b.x; acc[i][1] += av[i]*b.y;
                    acc[i][2] += av[i]*b.z; acc[i][3] += av[i]*b.w;
                }
            }
        }
    }
    float* fo = featptr(layer);
    float4 bb = *(const float4*)(bconv + layer*HD + tx*4);
    #pragma unroll
    for (int i=0;i<8;i++){
        int local = l0 + ty*8 + i;
        float4 o;
        o.x = fmaxf(acc[i][0]+bb.x, 0.f);
        o.y = fmaxf(acc[i][1]+bb.y, 0.f);
        o.z = fmaxf(acc[i][2]+bb.z, 0.f);
        o.w = fmaxf(acc[i][3]+bb.w, 0.f);
        *(float4*)(fo + (size_t)(g*NPG + local)*HD + tx*4) = o;
    }
}

// ---------------- node l2 norms (full chip, warp per node) ----------------
__global__ void k_l2(){
    int node = blockIdx.x*8 + (threadIdx.x >> 5);
    int lane = threadIdx.x & 31;
    size_t base = (size_t)node*HD + lane*4;
    float sq = 0.f;
    {
        float4 v;
        v = *(const float4*)(g_f0+base); sq += v.x*v.x+v.y*v.y+v.z*v.z+v.w*v.w;
        v = *(const float4*)(g_f1+base); sq += v.x*v.x+v.y*v.y+v.z*v.z+v.w*v.w;
        v = *(const float4*)(g_f2+base); sq += v.x*v.x+v.y*v.y+v.z*v.z+v.w*v.w;
        v = *(const float4*)(g_f3+base); sq += v.x*v.x+v.y*v.y+v.z*v.z+v.w*v.w;
    }
    #pragma unroll
    for (int o=16;o;o>>=1) sq += __shfl_xor_sync(0xffffffffu, sq, o);
    if (lane == 0) g_l2[node] = sq;
}

// ---------------- top-8 per graph + gather u, init Vcum ----------------
__global__ __launch_bounds__(1024) void k_top(){
    __shared__ float l2s[1024];
    __shared__ float rv[32]; __shared__ int ri[32];
    __shared__ int top8[8];
    int g = blockIdx.x, tid = threadIdx.x;
    int lane = tid & 31, warp = tid >> 5;
    l2s[tid] = g_l2[g*1024 + tid];
    __syncthreads();
    for (int t=0;t<8;t++){
        float v = l2s[tid]; int idx = tid;
        #pragma unroll
        for (int o=16;o;o>>=1){
            float v2 = __shfl_xor_sync(0xffffffffu, v, o);
            int   i2 = __shfl_xor_sync(0xffffffffu, idx, o);
            if (v2 > v || (v2 == v && i2 < idx)){ v = v2; idx = i2; }
        }
        if (lane == 0){ rv[warp] = v; ri[warp] = idx; }
        __syncthreads();
        if (warp == 0){
            float vv = rv[lane]; int ii = ri[lane];
            #pragma unroll
            for (int o=16;o;o>>=1){
                float v2 = __shfl_xor_sync(0xffffffffu, vv, o);
                int   i2 = __shfl_xor_sync(0xffffffffu, ii, o);
                if (v2 > vv || (v2 == vv && i2 < ii)){ vv = v2; ii = i2; }
            }
            if (lane == 0){ top8[t] = ii; l2s[ii] = -1e30f; }
        }
        __syncthreads();
    }
    int bcap = tid >> 7, hh = tid & 127;
    int node = top8[bcap];
    size_t nb = (size_t)(g*NPG + node)*HD + hh;
    float4 uv;
    uv.x = g_f0[nb]; uv.y = g_f1[nb]; uv.z = g_f2[nb]; uv.w = g_f3[nb];
    *(float4*)&g_u [(size_t)(g*1024 + tid)*4] = uv;
    *(float4*)&g_Vc[(size_t)(g*1024 + tid)*4] = uv;
}

// ---------------- VTS phase A: per-row max + 1/Z of alpha = u . Vcum ----------------
__global__ __launch_bounds__(256) void k_phaseA(){
    __shared__ __align__(16) float sV[4096];
    int g = blockIdx.x, tid = threadIdx.x;
    int row = blockIdx.y*256 + tid;
    for (int i=tid;i<4096;i+=256) sV[i] = g_Vc[(size_t)g*4096 + i];
    __syncthreads();
    float4 u = *(const float4*)&g_u[(size_t)(g*1024 + row)*4];
    float m0=-1e30f, m1=-1e30f, m2=-1e30f, m3=-1e30f;
    for (int j=0;j<1024;j+=4){
        float4 c0 = *(const float4*)&sV[(j+0)*4];
        float4 c1 = *(const float4*)&sV[(j+1)*4];
        float4 c2 = *(const float4*)&sV[(j+2)*4];
        float4 c3 = *(const float4*)&sV[(j+3)*4];
        m0 = fmaxf(m0, u.x*c0.x + u.y*c0.y + u.z*c0.z + u.w*c0.w);
        m1 = fmaxf(m1, u.x*c1.x + u.y*c1.y + u.z*c1.z + u.w*c1.w);
        m2 = fmaxf(m2, u.x*c2.x + u.y*c2.y + u.z*c2.z + u.w*c2.w);
        m3 = fmaxf(m3, u.x*c3.x + u.y*c3.y + u.z*c3.z + u.w*c3.w);
    }
    float m = fmaxf(fmaxf(m0,m1), fmaxf(m2,m3));
    float z0=0.f, z1=0.f, z2=0.f, z3=0.f;
    for (int j=0;j<1024;j+=4){
        float4 c0 = *(const float4*)&sV[(j+0)*4];
        float4 c1 = *(const float4*)&sV[(j+1)*4];
        float4 c2 = *(const float4*)&sV[(j+2)*4];
        float4 c3 = *(const float4*)&sV[(j+3)*4];
        z0 += __expf(u.x*c0.x + u.y*c0.y + u.z*c0.z + u.w*c0.w - m);
        z1 += __expf(u.x*c1.x + u.y*c1.y + u.z*c1.z + u.w*c1.w - m);
        z2 += __expf(u.x*c2.x + u.y*c2.y + u.z*c2.z + u.w*c2.w - m);
        z3 += __expf(u.x*c3.x + u.y*c3.y + u.z*c3.z + u.w*c3.w - m);
    }
    g_m [g*1024 + row] = m;
    g_iZ[g*1024 + row] = 1.f/((z0+z1)+(z2+z3));
}

// ---------------- VTS phase B: v_new = beta^T u ; accumulate or squash ----------------
__global__ __launch_bounds__(256) void k_phaseB(int last){
    __shared__ __align__(16) float sU[4096];
    __shared__ float sM[1024];
    __shared__ float sZ[1024];
    int g = blockIdx.x, tid = threadIdx.x;
    int col = blockIdx.y*256 + tid;
    for (int i=tid;i<4096;i+=256) sU[i] = g_u[(size_t)g*4096 + i];
    for (int i=tid;i<1024;i+=256){ sM[i] = g_m[g*1024+i]; sZ[i] = g_iZ[g*1024+i]; }
    __syncthreads();
    float4 c = *(const float4*)&g_Vc[(size_t)(g*1024 + col)*4];
    float a0=0.f, a1=0.f, a2=0.f, a3=0.f;
    #pragma unroll 4
    for (int i=0;i<1024;i++){
        float4 uu = *(const float4*)&sU[i*4];
        float s = uu.x*c.x + uu.y*c.y + uu.z*c.z + uu.w*c.w;
        float w = __expf(s - sM[i]) * sZ[i];
        a0 += w*uu.x; a1 += w*uu.y; a2 += w*uu.z; a3 += w*uu.w;
    }
    if (!last){
        float4 o; o.x=c.x+a0; o.y=c.y+a1; o.z=c.z+a2; o.w=c.w+a3;
        *(float4*)&g_Vc[(size_t)(g*1024 + col)*4] = o;
    } else {
        float sq = a0*a0 + a1*a1 + a2*a2 + a3*a3;
        float sc = sq/(1.f+sq)/(sqrtf(sq + 1e-10f) + 1e-8f);
        float4 o; o.x=a0*sc; o.y=a1*sc; o.z=a2*sc; o.w=a3*sc;
        *(float4*)&g_SC[(size_t)(g*1024 + col)*4] = o;
    }
}

__global__ void k_zero_zs(){ int i = blockIdx.x*256+threadIdx.x; if (i < NG*CS) g_zs[i] = 0.f; }

// ---------------- gamma = softmax_s(delta) ----------------
__global__ void k_gamma(){
    __shared__ float sd[3200];
    __shared__ float sm[64], sz[64];
    int base = blockIdx.x * 3200;
    int tid = threadIdx.x;
    for (int i=tid;i<3200;i+=256) sd[i] = g_delta[(size_t)base + i];
    __syncthreads();
    if (tid < 64){
        float m = -1e30f;
        for (int k=0;k<NCLS;k++) m = fmaxf(m, sd[tid*NCLS + k]);
        float Z = 0.f;
        for (int k=0;k<NCLS;k++) Z += __expf(sd[tid*NCLS + k] - m);
        sm[tid] = m; sz[tid] = 1.f/Z;
    }
    __syncthreads();
    for (int i=tid;i<3200;i+=256){
        int r = i / NCLS;
        g_gamma[(size_t)base + i] = __expf(sd[i] - sm[r]) * sz[r];
    }
}

// ---------------- zsum[b,c,s] = sum_{n,m} Wjm[n,c,s,m] * gamma[b,n,s]*SC[b,n,m] ----------------
// grid (50 s, 16 n-chunks), 512 threads; Wjm stays in L2, no v materialization.
__global__ __launch_bounds__(512) void k_zsum2(const float* __restrict__ Wjm, int round0){
    __shared__ __align__(16) float4 Ws4[64*16];   // [n][c]  (m in float4)
    __shared__ __align__(16) float4 Xs4[64*32];   // [n][b]
    int s = blockIdx.x;
    int n0 = blockIdx.y*64;
    int tid = threadIdx.x;
    const float4* W4 = (const float4*)Wjm;
    #pragma unroll
    for (int i = tid; i < 1024; i += 512){
        int n = i >> 4, c = i & 15;
        Ws4[i] = W4[(size_t)(n0+n)*800 + c*50 + s];
    }
    #pragma unroll
    for (int i = tid; i < 2048; i += 512){
        int n = i >> 5, b = i & 31;
        float ga = round0 ? 0.02f : g_gamma[(size_t)(b*1024 + n0 + n)*50 + s];
        float4 sc = *(const float4*)&g_SC[(size_t)(b*1024 + n0 + n)*4];
        float4 x; x.x = ga*sc.x; x.y = ga*sc.y; x.z = ga*sc.z; x.w = ga*sc.w;
        Xs4[n*32 + b] = x;
    }
    __syncthreads();
    int c = tid & 15, b = tid >> 4;
    float acc = 0.f;
    #pragma unroll 8
    for (int n = 0; n < 64; n++){
        float4 w = Ws4[n*16 + c];
        float4 x = Xs4[n*32 + b];
        acc += w.x*x.x + w.y*x.y + w.z*x.z + w.w*x.w;
    }
    atomicAdd(&g_zs[b*CS + c*NCLS + s], acc);
}

// ---------------- z = squash_c(zsum) ----------------
__global__ void k_zfin(){
    int b = blockIdx.x, s = threadIdx.x;
    if (s >= NCLS) return;
    float vals[DCCN]; float sq = 0.f;
    #pragma unroll
    for (int c=0;c<DCCN;c++){ float v = g_zs[b*CS + c*NCLS + s]; vals[c]=v; sq += v*v; }
    float sc = sq/(1.f+sq)/(sqrtf(sq + 1e-10f) + 1e-8f);
    #pragma unroll
    for (int c=0;c<DCCN;c++) g_z[b*CS + c*NCLS + s] = vals[c]*sc;
}

// ---------------- delta[b,n,s] (+)= sum_m SC[b,n,m] * sum_c Wjm[n,c,s,m]*z[b,c,s] --------------
// block per n, Wjm slice (12.8KB) in smem.
__global__ __launch_bounds__(512) void k_delta2(const float* __restrict__ Wjm, int accum){
    __shared__ __align__(16) float4 Ws4[800];     // [c*50+s]
    int n = blockIdx.x;
    int tid = threadIdx.x;
    const float4* W4 = (const float4*)Wjm + (size_t)n*800;
    for (int i = tid; i < 800; i += 512) Ws4[i] = W4[i];
    __syncthreads();
    for (int p = tid; p < 1600; p += 512){
        int b = p / 50, s = p % 50;
        float tx=0.f, ty=0.f, tz=0.f, tw=0.f;
        #pragma unroll
        for (int c = 0; c < 16; c++){
            float zv = g_z[b*CS + c*NCLS + s];
            float4 w = Ws4[c*50 + s];
            tx += w.x*zv; ty += w.y*zv; tz += w.z*zv; tw += w.w*zv;
        }
        float4 sc = *(const float4*)&g_SC[(size_t)(b*1024 + n)*4];
        float d = tx*sc.x + ty*sc.y + tz*sc.z + tw*sc.w;
        size_t o = (size_t)(b*1024 + n)*50 + s;
        g_delta[o] = accum ? (g_delta[o] + d) : d;
    }
}

// ---------------- logits ----------------
__global__ void k_logit(float* __restrict__ out){
    int b = blockIdx.x, s = threadIdx.x;
    if (s >= NCLS) return;
    float sq = 0.f;
    #pragma unroll
    for (int c=0;c<DCCN;c++){ float v = g_z[b*CS + c*NCLS + s]; sq += v*v; }
    float lg = sqrtf(sq + 1e-10f);
    out[b*NCLS + s] = lg;
    out[NG*NCLS + b*NCLS + s] = lg;
}

// ---------------- launch ----------------
extern "C" void kernel_launch(void* const* d_in, const int* in_sizes, int n_in,
                              void* d_out, int out_size){
    const int*   type_ids  = (const int*)  d_in[0];
    const int*   token_ids = (const int*)  d_in[1];
    const int*   src       = (const int*)  d_in[2];
    const float* lw        = (const float*)d_in[4];
    const float* rw        = (const float*)d_in[5];
    const float* temb      = (const float*)d_in[7];
    const float* kemb      = (const float*)d_in[8];
    const float* WL        = (const float*)d_in[9];
    const float* WR        = (const float*)d_in[10];
    const float* WT        = (const float*)d_in[11];
    const float* bconv     = (const float*)d_in[12];
    const float* Wjm       = (const float*)d_in[13];
    float* out = (float*)d_out;

    k_embed<<<NN*32/256, 256>>>(type_ids, token_ids, temb, kemb);
    for (int l = 0; l < NLAY; l++){
        k_gather<<<NPT*32/256, 256>>>(src, lw, rw, l);
        k_gemm<<<NPT/64, 256>>>(WL, WR, WT, bconv, l);
    }
    k_l2<<<NN/8, 256>>>();
    k_top<<<NG, 1024>>>();
    for (int it = 0; it < 3; it++){
        k_phaseA<<<dim3(NG,4), 256>>>();
        k_phaseB<<<dim3(NG,4), 256>>>(it == 2 ? 1 : 0);
    }
    // round 0 (gamma uniform = 1/50)
    k_zero_zs<<<(NG*CS + 255)/256, 256>>>();
    k_zsum2<<<dim3(NCLS,16), 512>>>(Wjm, 1);
    k_zfin<<<NG, 64>>>();
    k_delta2<<<NPG, 512>>>(Wjm, 0);
    // round 1
    k_gamma<<<NN*NCLS/3200, 256>>>();
    k_zero_zs<<<(NG*CS + 255)/256, 256>>>();
    k_zsum2<<<dim3(NCLS,16), 512>>>(Wjm, 0);
    k_zfin<<<NG, 64>>>();
    k_delta2<<<NPG, 512>>>(Wjm, 1);
    // round 2 (final)
    k_gamma<<<NN*NCLS/3200, 256>>>();
    k_zero_zs<<<(NG*CS + 255)/256, 256>>>();
    k_zsum2<<<dim3(NCLS,16), 512>>>(Wjm, 0);
    k_zfin<<<NG, 64>>>();
    k_logit<<<NG, 64>>>(out);
}

// round 5
// speedup vs baseline: 1.6212x; 1.3378x over previous
#include <cuda_runtime.h>
#include <cuda_bf16.h>
#include <cstdint>

#define NG   32
#define NPG  1024
#define NN   (NG*NPG)
#define HD   128
#define NLAY 4
#define NPAR 256
#define NPT  (NG*NPAR)
#define NCLS 50
#define DCCN 16
#define CS   (DCCN*NCLS)   // 800

typedef unsigned long long u64t;

__device__ __forceinline__ u64t pk2(float x, float y){ u64t r; asm("mov.b64 %0, {%1,%2};" : "=l"(r) : "f"(x), "f"(y)); return r; }
__device__ __forceinline__ void upk2(u64t p, float& x, float& y){ asm("mov.b64 {%0,%1}, %2;" : "=f"(x), "=f"(y) : "l"(p)); }
__device__ __forceinline__ u64t fma2_(u64t a, u64t b, u64t c){ u64t d; asm("fma.rn.f32x2 %0, %1, %2, %3;" : "=l"(d) : "l"(a), "l"(b), "l"(c)); return d; }
__device__ __forceinline__ u64t mul2_(u64t a, u64t b){ u64t d; asm("mul.rn.f32x2 %0, %1, %2;" : "=l"(d) : "l"(a), "l"(b)); return d; }
__device__ __forceinline__ u64t add2_(u64t a, u64t b){ u64t d; asm("add.rn.f32x2 %0, %1, %2;" : "=l"(d) : "l"(a), "l"(b)); return d; }

// ---------------- device scratch ----------------
__device__ __align__(256) float g_h0[NN*HD];
__device__ __align__(256) float g_f0[NN*HD];
__device__ __align__(256) float g_f1[NN*HD];
__device__ __align__(256) float g_f2[NN*HD];
__device__ __align__(256) float g_f3[NN*HD];
__device__ __align__(256) float g_l2[NN];
__device__ __align__(256) float g_u [NG*1024*4];
__device__ __align__(256) float g_Vc[NG*1024*4];
__device__ __align__(256) float g_m [NG*1024];   // stores NEGATED row max
__device__ __align__(256) float g_iZ[NG*1024];
__device__ __align__(256) float g_SC[NG*1024*4];
__device__ __align__(256) float g_delta[NN*NCLS];
__device__ __align__(256) float g_gamma[NN*NCLS];
__device__ __align__(256) float g_zs[NG*CS];
__device__ __align__(256) float g_z [NG*CS];

__device__ __forceinline__ float* featptr(int l){
    switch(l){ case 0: return g_f0; case 1: return g_f1; case 2: return g_f2; default: return g_f3; }
}

// ---------------- embedding + leaf prefill + leaf l2 ----------------
__global__ void k_embed(const int* __restrict__ type_ids, const int* __restrict__ token_ids,
                        const float* __restrict__ temb, const float* __restrict__ kemb){
    int idx = blockIdx.x*256 + threadIdx.x;          // n*32 + q  (warp == one node)
    int n = idx >> 5, q = idx & 31;
    float4 v;
    if (q < 16) v = *(const float4*)(temb + (size_t)type_ids[n]*64 + q*4);
    else        v = *(const float4*)(kemb + (size_t)token_ids[n]*64 + (q-16)*4);
    size_t o = (size_t)n*HD + q*4;
    *(float4*)(g_h0 + o) = v;
    bool leaf = (n & (NPG-1)) >= NPAR;
    if (leaf){
        *(float4*)(g_f0+o)=v; *(float4*)(g_f1+o)=v; *(float4*)(g_f2+o)=v; *(float4*)(g_f3+o)=v;
    }
    float sq = v.x*v.x + v.y*v.y + v.z*v.z + v.w*v.w;
    #pragma unroll
    for (int s=16;s;s>>=1) sq += __shfl_xor_sync(0xffffffffu, sq, s);
    if (q == 0) g_l2[n] = leaf ? 4.f*sq : 0.f;
}

// ---------------- fused gather + GEMM + bias/relu + l2 accumulation ----------------
// feats[l] = relu(GL@WL + GR@WR + Hp@WT + b)  on parent rows; GL/GR built in smem per k-chunk.
__global__ __launch_bounds__(256) void k_gemm(const float* __restrict__ WLp,
        const float* __restrict__ WRp, const float* __restrict__ WTp,
        const float* __restrict__ bconv,
        const float* __restrict__ lw, const float* __restrict__ rw, int layer){
    __shared__ __align__(16) float GLx[16][72];
    __shared__ __align__(16) float GRx[16][72];
    __shared__ __align__(16) float Xs [16][72];
    __shared__ __align__(16) float Ws3[3][16][128];
    __shared__ float lw_s[256], rw_s[256];
    const int tid = threadIdx.x;
    const int row0 = blockIdx.x*64;                  // parent row [0,8192)
    const int g = row0 >> 8, l0 = row0 & 255;
    const float* hin = (layer==0) ? g_h0 : featptr(layer-1);
    const float* Wb[3] = { WLp + layer*HD*HD, WRp + layer*HD*HD, WTp + layer*HD*HD };
    const int ty = tid >> 5, tx = tid & 31;

    // stage edge weights for this tile (edges 4*l0 .. 4*l0+255 local)
    {
        int e_local = 4*l0 + tid;
        bool valid = e_local < 1023;
        lw_s[tid] = valid ? lw[g*1023 + e_local] : 0.f;
        rw_s[tid] = valid ? rw[g*1023 + e_local] : 0.f;
    }

    u64t acc2[4][4];                                  // [rowpair][col], halves = (row 2rp, 2rp+1)
    #pragma unroll
    for (int i=0;i<4;i++){ acc2[i][0]=0; acc2[i][1]=0; acc2[i][2]=0; acc2[i][3]=0; }

    const int p_rel = tid >> 2, q = tid & 3;
    for (int k0 = 0; k0 < HD; k0 += 16){
        __syncthreads();
        // parent tile
        {
            float4 v = *(const float4*)(hin + (size_t)(g*NPG + l0 + p_rel)*HD + k0 + q*4);
            Xs[q*4+0][p_rel]=v.x; Xs[q*4+1][p_rel]=v.y; Xs[q*4+2][p_rel]=v.z; Xs[q*4+3][p_rel]=v.w;
        }
        // gathered child tiles
        {
            float glx=0,gly=0,glz=0,glw=0, grx=0,gry=0,grz=0,grw=0;
            #pragma unroll
            for (int j=0;j<4;j++){
                float wl = lw_s[p_rel*4+j], wr = rw_s[p_rel*4+j];
                int c_local = 4*(l0+p_rel) + 1 + j;
                if (c_local > 1023) c_local = 1023;   // weight already 0
                float4 cv = *(const float4*)(hin + (size_t)(g*NPG + c_local)*HD + k0 + q*4);
                glx += wl*cv.x; gly += wl*cv.y; glz += wl*cv.z; glw += wl*cv.w;
                grx += wr*cv.x; gry += wr*cv.y; grz += wr*cv.z; grw += wr*cv.w;
            }
            GLx[q*4+0][p_rel]=glx; GLx[q*4+1][p_rel]=gly; GLx[q*4+2][p_rel]=glz; GLx[q*4+3][p_rel]=glw;
            GRx[q*4+0][p_rel]=grx; GRx[q*4+1][p_rel]=gry; GRx[q*4+2][p_rel]=grz; GRx[q*4+3][p_rel]=grw;
        }
        // weight chunks for all 3 segments
        #pragma unroll
        for (int i=0;i<6;i++){
            int qq = tid + i*256;                     // 0..1535
            int seg = qq >> 9, r = qq & 511;
            int k = r >> 5, n4 = r & 31;
            *(float4*)&Ws3[seg][k][n4*4] = *(const float4*)(Wb[seg] + (size_t)(k0+k)*HD + n4*4);
        }
        __syncthreads();
        #pragma unroll 4
        for (int k=0;k<16;k++){
            #pragma unroll
            for (int seg=0;seg<3;seg++){
                float4 b = *(const float4*)&Ws3[seg][k][tx*4];
                u64t B0 = pk2(b.x,b.x), B1 = pk2(b.y,b.y), B2 = pk2(b.z,b.z), B3 = pk2(b.w,b.w);
                const float* As = (seg==0) ? &GLx[k][0] : (seg==1) ? &GRx[k][0] : &Xs[k][0];
                #pragma unroll
                for (int rp=0;rp<4;rp++){
                    u64t ap = pk2(As[ty*8+rp*2], As[ty*8+rp*2+1]);
                    acc2[rp][0] = fma2_(ap, B0, acc2[rp][0]);
                    acc2[rp][1] = fma2_(ap, B1, acc2[rp][1]);
                    acc2[rp][2] = fma2_(ap, B2, acc2[rp][2]);
                    acc2[rp][3] = fma2_(ap, B3, acc2[rp][3]);
                }
            }
        }
    }
    // epilogue: bias + relu + store + l2 atomic per row
    float* fo = featptr(layer);
    float4 bb = *(const float4*)(bconv + layer*HD + tx*4);
    #pragma unroll
    for (int rp=0;rp<4;rp++){
        float r0[4], r1[4];
        upk2(acc2[rp][0], r0[0], r1[0]);
        upk2(acc2[rp][1], r0[1], r1[1]);
        upk2(acc2[rp][2], r0[2], r1[2]);
        upk2(acc2[rp][3], r0[3], r1[3]);
        float bv[4] = {bb.x, bb.y, bb.z, bb.w};
        float sq0 = 0.f, sq1 = 0.f;
        #pragma unroll
        for (int c=0;c<4;c++){
            r0[c] = fmaxf(r0[c]+bv[c], 0.f);
            r1[c] = fmaxf(r1[c]+bv[c], 0.f);
            sq0 += r0[c]*r0[c]; sq1 += r1[c]*r1[c];
        }
        int loc0 = l0 + ty*8 + rp*2;
        float4 o0 = {r0[0],r0[1],r0[2],r0[3]};
        float4 o1 = {r1[0],r1[1],r1[2],r1[3]};
        *(float4*)(fo + (size_t)(g*NPG + loc0  )*HD + tx*4) = o0;
        *(float4*)(fo + (size_t)(g*NPG + loc0+1)*HD + tx*4) = o1;
        #pragma unroll
        for (int s=16;s;s>>=1){ sq0 += __shfl_xor_sync(0xffffffffu, sq0, s);
                                sq1 += __shfl_xor_sync(0xffffffffu, sq1, s); }
        if (tx == 0){
            atomicAdd(&g_l2[g*NPG + loc0  ], sq0);
            atomicAdd(&g_l2[g*NPG + loc0+1], sq1);
        }
    }
}

// ---------------- top-8 per graph + gather u, init Vcum ----------------
__global__ __launch_bounds__(1024) void k_top(){
    __shared__ float l2s[1024];
    __shared__ float rv[32]; __shared__ int ri[32];
    __shared__ int top8[8];
    int g = blockIdx.x, tid = threadIdx.x;
    int lane = tid & 31, warp = tid >> 5;
    l2s[tid] = g_l2[g*1024 + tid];
    __syncthreads();
    for (int t=0;t<8;t++){
        float v = l2s[tid]; int idx = tid;
        #pragma unroll
        for (int o=16;o;o>>=1){
            float v2 = __shfl_xor_sync(0xffffffffu, v, o);
            int   i2 = __shfl_xor_sync(0xffffffffu, idx, o);
            if (v2 > v || (v2 == v && i2 < idx)){ v = v2; idx = i2; }
        }
        if (lane == 0){ rv[warp] = v; ri[warp] = idx; }
        __syncthreads();
        if (warp == 0){
            float vv = rv[lane]; int ii = ri[lane];
            #pragma unroll
            for (int o=16;o;o>>=1){
                float v2 = __shfl_xor_sync(0xffffffffu, vv, o);
                int   i2 = __shfl_xor_sync(0xffffffffu, ii, o);
                if (v2 > vv || (v2 == vv && i2 < ii)){ vv = v2; ii = i2; }
            }
            if (lane == 0){ top8[t] = ii; l2s[ii] = -1e30f; }
        }
        __syncthreads();
    }
    int bcap = tid >> 7, hh = tid & 127;
    int node = top8[bcap];
    size_t nb = (size_t)(g*NPG + node)*HD + hh;
    float4 uv;
    uv.x = g_f0[nb]; uv.y = g_f1[nb]; uv.z = g_f2[nb]; uv.w = g_f3[nb];
    *(float4*)&g_u [(size_t)(g*1024 + tid)*4] = uv;
    *(float4*)&g_Vc[(size_t)(g*1024 + tid)*4] = uv;
}

// ---------------- VTS phase A: per-row (neg)max + 1/Z of alpha = u . Vcum ----------------
__global__ __launch_bounds__(256) void k_phaseA(){
    __shared__ __align__(16) ulonglong2 sVp2[1024];   // pair-packed Vc: [jp]{(x,x),(y,y)},{(z,z),(w,w)}
    int g = blockIdx.x, tid = threadIdx.x;
    int row = blockIdx.y*256 + tid;
    for (int i=tid;i<512;i+=256){
        float4 c0 = *(const float4*)&g_Vc[(size_t)(g*1024 + 2*i  )*4];
        float4 c1 = *(const float4*)&g_Vc[(size_t)(g*1024 + 2*i+1)*4];
        ulonglong2 A, B;
        A.x = pk2(c0.x,c1.x); A.y = pk2(c0.y,c1.y);
        B.x = pk2(c0.z,c1.z); B.y = pk2(c0.w,c1.w);
        sVp2[i*2] = A; sVp2[i*2+1] = B;
    }
    __syncthreads();
    float4 u = *(const float4*)&g_u[(size_t)(g*1024 + row)*4];
    u64t U0 = pk2(u.x,u.x), U1 = pk2(u.y,u.y), U2 = pk2(u.z,u.z), U3 = pk2(u.w,u.w);
    float m = -1e30f;
    #pragma unroll 4
    for (int jp=0;jp<512;jp++){
        ulonglong2 P01 = sVp2[jp*2], P23 = sVp2[jp*2+1];
        u64t t = mul2_(U0, P01.x); t = fma2_(U1, P01.y, t);
        t = fma2_(U2, P23.x, t);   t = fma2_(U3, P23.y, t);
        float s0, s1; upk2(t, s0, s1);
        m = fmaxf(m, fmaxf(s0, s1));
    }
    float mn = -m;
    u64t MN = pk2(mn, mn);
    float z = 0.f;
    #pragma unroll 4
    for (int jp=0;jp<512;jp++){
        ulonglong2 P01 = sVp2[jp*2], P23 = sVp2[jp*2+1];
        u64t t = mul2_(U0, P01.x); t = fma2_(U1, P01.y, t);
        t = fma2_(U2, P23.x, t);   t = fma2_(U3, P23.y, t);
        t = add2_(t, MN);
        float s0, s1; upk2(t, s0, s1);
        z += __expf(s0); z += __expf(s1);
    }
    g_m [g*1024 + row] = mn;
    g_iZ[g*1024 + row] = 1.f/z;
}

// ---------------- VTS phase B: v_new = beta^T u ; accumulate or squash ----------------
__global__ __launch_bounds__(256) void k_phaseB(int last){
    __shared__ __align__(16) ulonglong2 sUp2[1024];   // pair-packed u (over rows i)
    __shared__ __align__(16) float4 sUn[1024];        // natural u
    __shared__ u64t sMn2[512];                        // (negmax pairs)
    __shared__ u64t sZ2[512];                         // (iZ pairs)
    int g = blockIdx.x, tid = threadIdx.x;
    int col = blockIdx.y*256 + tid;
    for (int i=tid;i<512;i+=256){
        float4 u0 = *(const float4*)&g_u[(size_t)(g*1024 + 2*i  )*4];
        float4 u1 = *(const float4*)&g_u[(size_t)(g*1024 + 2*i+1)*4];
        sUn[2*i] = u0; sUn[2*i+1] = u1;
        ulonglong2 A, B;
        A.x = pk2(u0.x,u1.x); A.y = pk2(u0.y,u1.y);
        B.x = pk2(u0.z,u1.z); B.y = pk2(u0.w,u1.w);
        sUp2[i*2] = A; sUp2[i*2+1] = B;
        sMn2[i] = pk2(g_m [g*1024+2*i], g_m [g*1024+2*i+1]);
        sZ2 [i] = pk2(g_iZ[g*1024+2*i], g_iZ[g*1024+2*i+1]);
    }
    __syncthreads();
    float4 c = *(const float4*)&g_Vc[(size_t)(g*1024 + col)*4];
    u64t C0 = pk2(c.x,c.x), C1 = pk2(c.y,c.y), C2 = pk2(c.z,c.z), C3 = pk2(c.w,c.w);
    u64t a01 = 0, a23 = 0;
    #pragma unroll 2
    for (int ip=0;ip<512;ip++){
        ulonglong2 P01 = sUp2[ip*2], P23 = sUp2[ip*2+1];
        u64t t = mul2_(C0, P01.x); t = fma2_(C1, P01.y, t);
        t = fma2_(C2, P23.x, t);   t = fma2_(C3, P23.y, t);
        t = add2_(t, sMn2[ip]);
        float s0, s1; upk2(t, s0, s1);
        float e0 = __expf(s0), e1 = __expf(s1);
        u64t wz = mul2_(pk2(e0,e1), sZ2[ip]);
        float w0, w1; upk2(wz, w0, w1);
        u64t W0 = pk2(w0,w0), W1 = pk2(w1,w1);
        ulonglong2 Ua = *(const ulonglong2*)&sUn[2*ip];
        ulonglong2 Ub = *(const ulonglong2*)&sUn[2*ip+1];
        a01 = fma2_(W0, Ua.x, a01); a23 = fma2_(W0, Ua.y, a23);
        a01 = fma2_(W1, Ub.x, a01); a23 = fma2_(W1, Ub.y, a23);
    }
    float a0,a1,a2,a3;
    upk2(a01, a0, a1); upk2(a23, a2, a3);
    if (!last){
        float4 o; o.x=c.x+a0; o.y=c.y+a1; o.z=c.z+a2; o.w=c.w+a3;
        *(float4*)&g_Vc[(size_t)(g*1024 + col)*4] = o;
    } else {
        float sq = a0*a0 + a1*a1 + a2*a2 + a3*a3;
        float sc = sq/(1.f+sq)/(sqrtf(sq + 1e-10f) + 1e-8f);
        float4 o; o.x=a0*sc; o.y=a1*sc; o.z=a2*sc; o.w=a3*sc;
        *(float4*)&g_SC[(size_t)(g*1024 + col)*4] = o;
    }
}

// ---------------- zsum[b,c,s] = sum_{n,m} Wjm[n,c,s,m] * gamma[b,n,s]*SC[b,n,m] ----------------
__global__ __launch_bounds__(512) void k_zsum2(const float* __restrict__ Wjm, int round0){
    __shared__ __align__(16) float4 Ws4[64*16];   // [n][c]
    __shared__ __align__(16) float4 Xs4[64*32];   // [n][b]
    int s = blockIdx.x;
    int n0 = blockIdx.y*64;
    int tid = threadIdx.x;
    const float4* W4 = (const float4*)Wjm;
    #pragma unroll
    for (int i = tid; i < 1024; i += 512){
        int n = i >> 4, c = i & 15;
        Ws4[i] = W4[(size_t)(n0+n)*800 + c*50 + s];
    }
    #pragma unroll
    for (int i = tid; i < 2048; i += 512){
        int n = i >> 5, b = i & 31;
        float ga = round0 ? 0.02f : g_gamma[(size_t)(b*1024 + n0 + n)*50 + s];
        float4 sc = *(const float4*)&g_SC[(size_t)(b*1024 + n0 + n)*4];
        float4 x; x.x = ga*sc.x; x.y = ga*sc.y; x.z = ga*sc.z; x.w = ga*sc.w;
        Xs4[n*32 + b] = x;
    }
    __syncthreads();
    int c = tid & 15, b = tid >> 4;
    float acc = 0.f;
    #pragma unroll 8
    for (int n = 0; n < 64; n++){
        float4 w = Ws4[n*16 + c];
        float4 x = Xs4[n*32 + b];
        acc += w.x*x.x + w.y*x.y + w.z*x.z + w.w*x.w;
    }
    atomicAdd(&g_zs[b*CS + c*NCLS + s], acc);
}

// ---------------- z = squash_c(zsum); re-zero zs for next round ----------------
__global__ void k_zfin(){
    int b = blockIdx.x, s = threadIdx.x;
    if (s >= NCLS) return;
    float vals[DCCN]; float sq = 0.f;
    #pragma unroll
    for (int c=0;c<DCCN;c++){
        float v = g_zs[b*CS + c*NCLS + s]; vals[c]=v; sq += v*v;
        g_zs[b*CS + c*NCLS + s] = 0.f;
    }
    float sc = sq/(1.f+sq)/(sqrtf(sq + 1e-10f) + 1e-8f);
    #pragma unroll
    for (int c=0;c<DCCN;c++) g_z[b*CS + c*NCLS + s] = vals[c]*sc;
}

// ---------------- fused: delta update + gamma = softmax_s(delta) ----------------
__global__ __launch_bounds__(512) void k_dg(const float* __restrict__ Wjm, int accum){
    __shared__ __align__(16) float4 Ws4[800];
    __shared__ float sdel[1600];
    __shared__ float smx[32], siz[32];
    int n = blockIdx.x;
    int tid = threadIdx.x;
    const float4* W4 = (const float4*)Wjm + (size_t)n*800;
    for (int i = tid; i < 800; i += 512) Ws4[i] = W4[i];
    __syncthreads();
    for (int p = tid; p < 1600; p += 512){
        int b = p / 50, s = p % 50;
        float tx=0.f, ty=0.f, tz=0.f, tw=0.f;
        #pragma unroll
        for (int c = 0; c < 16; c++){
            float zv = g_z[b*CS + c*NCLS + s];
            float4 w = Ws4[c*50 + s];
            tx += w.x*zv; ty += w.y*zv; tz += w.z*zv; tw += w.w*zv;
        }
        float4 sc = *(const float4*)&g_SC[(size_t)(b*1024 + n)*4];
        float d = tx*sc.x + ty*sc.y + tz*sc.z + tw*sc.w;
        size_t o = (size_t)(b*1024 + n)*50 + s;
        if (accum) d += g_delta[o];
        g_delta[o] = d;
        sdel[p] = d;
    }
    __syncthreads();
    if (tid < 32){
        float m = -1e30f;
        for (int k=0;k<NCLS;k++) m = fmaxf(m, sdel[tid*50 + k]);
        float Z = 0.f;
        for (int k=0;k<NCLS;k++) Z += __expf(sdel[tid*50 + k] - m);
        smx[tid] = m; siz[tid] = 1.f/Z;
    }
    __syncthreads();
    for (int p = tid; p < 1600; p += 512){
        int b = p / 50;
        size_t o = (size_t)(b*1024 + n)*50 + (p % 50);
        g_gamma[o] = __expf(sdel[p] - smx[b]) * siz[b];
    }
}

// ---------------- logits ----------------
__global__ void k_logit(float* __restrict__ out){
    int b = blockIdx.x, s = threadIdx.x;
    if (s >= NCLS) return;
    float sq = 0.f;
    #pragma unroll
    for (int c=0;c<DCCN;c++){ float v = g_z[b*CS + c*NCLS + s]; sq += v*v; }
    float lg = sqrtf(sq + 1e-10f);
    out[b*NCLS + s] = lg;
    out[NG*NCLS + b*NCLS + s] = lg;
}

// ---------------- launch ----------------
extern "C" void kernel_launch(void* const* d_in, const int* in_sizes, int n_in,
                              void* d_out, int out_size){
    const int*   type_ids  = (const int*)  d_in[0];
    const int*   token_ids = (const int*)  d_in[1];
    const float* lw        = (const float*)d_in[4];
    const float* rw        = (const float*)d_in[5];
    const float* temb      = (const float*)d_in[7];
    const float* kemb      = (const float*)d_in[8];
    const float* WL        = (const float*)d_in[9];
    const float* WR        = (const float*)d_in[10];
    const float* WT        = (const float*)d_in[11];
    const float* bconv     = (const float*)d_in[12];
    const float* Wjm       = (const float*)d_in[13];
    float* out = (float*)d_out;

    k_embed<<<NN*32/256, 256>>>(type_ids, token_ids, temb, kemb);
    for (int l = 0; l < NLAY; l++)
        k_gemm<<<NPT/64, 256>>>(WL, WR, WT, bconv, lw, rw, l);
    k_top<<<NG, 1024>>>();
    for (int it = 0; it < 3; it++){
        k_phaseA<<<dim3(NG,4), 256>>>();
        k_phaseB<<<dim3(NG,4), 256>>>(it == 2 ? 1 : 0);
    }
    // round 0 (gamma uniform = 1/50)
    k_zsum2<<<dim3(NCLS,16), 512>>>(Wjm, 1);
    k_zfin<<<NG, 64>>>();
    k_dg<<<NPG, 512>>>(Wjm, 0);
    // round 1
    k_zsum2<<<dim3(NCLS,16), 512>>>(Wjm, 0);
    k_zfin<<<NG, 64>>>();
    k_dg<<<NPG, 512>>>(Wjm, 1);
    // round 2 (final)
    k_zsum2<<<dim3(NCLS,16), 512>>>(Wjm, 0);
    k_zfin<<<NG, 64>>>();
    k_logit<<<NG, 64>>>(out);
}